// round 2
// baseline (speedup 1.0000x reference)
#include <cuda_runtime.h>

// Problem constants
#define B_TOTAL 131072
#define T_SEQ   5
#define I_DIM   13
#define H_DIM   256
#define G_DIM   1024   // 4*H
#define OUT_DIM 6

// Kernel config
#define BT      16     // batch rows per block
#define THREADS 256
#define HP      260    // padded pitch for h shared rows (avoids proj-phase bank conflicts)

// -------- device scratch (allocation-free rule: __device__ globals) --------
__device__ float g_Wt [H_DIM * G_DIM];  // transposed W_hh: [k][g]
__device__ float g_Wit[I_DIM * G_DIM];  // transposed W_ih: [i][g]
__device__ float g_bs [G_DIM];          // b_ih + b_hh

// ---------------------------------------------------------------------------
__global__ void prep_kernel(const float* __restrict__ W_ih,
                            const float* __restrict__ W_hh,
                            const float* __restrict__ b_ih,
                            const float* __restrict__ b_hh) {
    int idx = blockIdx.x * blockDim.x + threadIdx.x;
    int stride = gridDim.x * blockDim.x;
    for (int e = idx; e < H_DIM * G_DIM; e += stride) {
        int k = e / G_DIM, g = e % G_DIM;
        g_Wt[e] = W_hh[g * H_DIM + k];
    }
    for (int e = idx; e < I_DIM * G_DIM; e += stride) {
        int i = e / G_DIM, g = e % G_DIM;
        g_Wit[e] = W_ih[g * I_DIM + i];
    }
    for (int e = idx; e < G_DIM; e += stride)
        g_bs[e] = b_ih[e] + b_hh[e];
}

// ---- accurate fast activations (MUFU EX2/RCP path, err ~1e-6) -------------
__device__ __forceinline__ float sigmoid_f(float x) {
    // x = +large -> expf(-x)=0 -> 1 ; x = -large -> expf(-x)=inf -> 0. Safe.
    return 1.0f / (1.0f + __expf(-x));
}
__device__ __forceinline__ float tanh_f(float x) {
    float a = fabsf(x);
    float e = __expf(-2.0f * a);          // in (0,1], no overflow
    float r = (1.0f - e) / (1.0f + e);
    return copysignf(r, x);
}

// ---------------------------------------------------------------------------
__global__ __launch_bounds__(THREADS, 1)
void lstm_kernel(const float* __restrict__ x,    // [B, T, I]
                 const float* __restrict__ W1,   // [OUT, T*H]
                 const float* __restrict__ b1,   // [OUT]
                 float* __restrict__ out) {      // [B, OUT]
    __shared__ float h_s[2][BT][HP];
    __shared__ float x_s[BT][T_SEQ][I_DIM];

    const int tid = threadIdx.x;
    const int b0  = blockIdx.x * BT;
    const int hu  = tid;  // each thread owns one hidden unit (0..255)

    // Stage input tile into shared
    for (int e = tid; e < BT * T_SEQ * I_DIM; e += THREADS) {
        int b = e / (T_SEQ * I_DIM), r = e % (T_SEQ * I_DIM);
        x_s[b][r / I_DIM][r % I_DIM] = x[(size_t)(b0 + b) * (T_SEQ * I_DIM) + r];
    }
    // h0 = 0
    for (int e = tid; e < BT * HP; e += THREADS)
        (&h_s[0][0][0])[e] = 0.0f;

    // Per-thread gate biases (row hu of each of the 4 gates)
    float bsum[4];
    #pragma unroll
    for (int g = 0; g < 4; g++) bsum[g] = g_bs[g * H_DIM + hu];

    // Cell state: thread t owns c[b][hu] for all BT batch rows
    float c[BT];
    #pragma unroll
    for (int j = 0; j < BT; j++) c[j] = 0.0f;

    // Output-head ownership: threads 0..BT*OUT-1 each own one (b, o) pair
    const int  pb = tid / OUT_DIM, po = tid % OUT_DIM;
    const bool do_proj = (tid < BT * OUT_DIM);
    float oacc = 0.0f;

    __syncthreads();

    int cur = 0;
    for (int t = 0; t < T_SEQ; t++) {
        const int nxt = cur ^ 1;

        float acc[4][BT];
        #pragma unroll
        for (int g = 0; g < 4; g++)
            #pragma unroll
            for (int j = 0; j < BT; j++) acc[g][j] = bsum[g];

        // ---- input projection: K = 13 ----
        #pragma unroll
        for (int i = 0; i < I_DIM; i++) {
            const float w0 = g_Wit[i * G_DIM +             hu];
            const float w1 = g_Wit[i * G_DIM +     H_DIM + hu];
            const float w2 = g_Wit[i * G_DIM + 2 * H_DIM + hu];
            const float w3 = g_Wit[i * G_DIM + 3 * H_DIM + hu];
            #pragma unroll
            for (int j = 0; j < BT; j++) {
                const float xv = x_s[j][t][i];          // warp-broadcast LDS
                acc[0][j] = fmaf(xv, w0, acc[0][j]);
                acc[1][j] = fmaf(xv, w1, acc[1][j]);
                acc[2][j] = fmaf(xv, w2, acc[2][j]);
                acc[3][j] = fmaf(xv, w3, acc[3][j]);
            }
        }

        // ---- hidden projection: K = 256 (the hot loop) ----
        #pragma unroll 2
        for (int k = 0; k < H_DIM; k++) {
            const float w0 = g_Wt[k * G_DIM +             hu];   // coalesced
            const float w1 = g_Wt[k * G_DIM +     H_DIM + hu];
            const float w2 = g_Wt[k * G_DIM + 2 * H_DIM + hu];
            const float w3 = g_Wt[k * G_DIM + 3 * H_DIM + hu];
            #pragma unroll
            for (int j = 0; j < BT; j++) {
                const float hv = h_s[cur][j][k];        // warp-broadcast LDS
                acc[0][j] = fmaf(hv, w0, acc[0][j]);
                acc[1][j] = fmaf(hv, w1, acc[1][j]);
                acc[2][j] = fmaf(hv, w2, acc[2][j]);
                acc[3][j] = fmaf(hv, w3, acc[3][j]);
            }
        }

        // ---- gates, state update, write h(t) into the other buffer ----
        #pragma unroll
        for (int j = 0; j < BT; j++) {
            const float ig = sigmoid_f(acc[0][j]);
            const float fg = sigmoid_f(acc[1][j]);
            const float gg = tanh_f   (acc[2][j]);
            const float og = sigmoid_f(acc[3][j]);
            const float cn = fmaf(fg, c[j], ig * gg);
            c[j] = cn;
            h_s[nxt][j][hu] = og * tanh_f(cn);          // conflict-free STS
        }
        __syncthreads();   // h(t) complete & visible

        // ---- fold output head for this timestep (tiny) ----
        if (do_proj) {
            const float* w1p = W1 + (size_t)po * (T_SEQ * H_DIM) + t * H_DIM;
            float s = 0.0f;
            #pragma unroll 4
            for (int k = 0; k < H_DIM; k++)
                s = fmaf(h_s[nxt][pb][k], w1p[k], s);
            oacc += s;
        }
        cur = nxt;
        // No extra sync needed: next iter writes the *other* buffer; the buffer
        // the projection reads isn't re-written until after the next sync.
    }

    if (do_proj)
        out[(size_t)(b0 + pb) * OUT_DIM + po] = oacc + b1[po];
}

// ---------------------------------------------------------------------------
extern "C" void kernel_launch(void* const* d_in, const int* in_sizes, int n_in,
                              void* d_out, int out_size) {
    const float* x    = (const float*)d_in[0];  // input_seq [B,5,13]
    const float* W_ih = (const float*)d_in[1];  // [1024,13]
    const float* W_hh = (const float*)d_in[2];  // [1024,256]
    const float* b_ih = (const float*)d_in[3];  // [1024]
    const float* b_hh = (const float*)d_in[4];  // [1024]
    const float* W1   = (const float*)d_in[5];  // [6,1280]
    const float* b1   = (const float*)d_in[6];  // [6]
    float* out = (float*)d_out;                 // [B,6]

    prep_kernel<<<256, 256>>>(W_ih, W_hh, b_ih, b_hh);
    lstm_kernel<<<B_TOTAL / BT, THREADS>>>(x, W1, b1, out);
}

// round 3
// speedup vs baseline: 2.0652x; 2.0652x over previous
#include <cuda_runtime.h>

// Problem constants
#define B_TOTAL 131072
#define T_SEQ   5
#define I_DIM   13
#define H_DIM   256
#define G_DIM   1024   // 4*H
#define OUT_DIM 6

// Kernel config
#define BT      16     // batch rows per block
#define NPAIR   (BT/2)
#define THREADS 256
#define HPITCH  (BT + 2)   // 18: even (8B-aligned pairs), 18 coprime-ish banks for STS

typedef unsigned long long u64;

// -------- device scratch (allocation-free rule: __device__ globals) --------
// Weights repacked as [k][hu][4 gates] float4 -> one LDG.128 per k per thread
__device__ float4 g_Wt4 [H_DIM * H_DIM];   // [k][hu] -> (w_i, w_f, w_g, w_o)
__device__ float4 g_Wit4[I_DIM * H_DIM];   // [i][hu] -> (w_i, w_f, w_g, w_o)
__device__ float  g_bs  [G_DIM];           // b_ih + b_hh

// ---------------------------------------------------------------------------
__global__ void prep_kernel(const float* __restrict__ W_ih,
                            const float* __restrict__ W_hh,
                            const float* __restrict__ b_ih,
                            const float* __restrict__ b_hh) {
    int idx = blockIdx.x * blockDim.x + threadIdx.x;
    int stride = gridDim.x * blockDim.x;
    // g_Wt4[k*H + hu].g = W_hh[(g*H + hu) * H + k]
    for (int e = idx; e < H_DIM * H_DIM; e += stride) {
        int k = e / H_DIM, hu = e % H_DIM;
        float4 w;
        w.x = W_hh[(0 * H_DIM + hu) * H_DIM + k];
        w.y = W_hh[(1 * H_DIM + hu) * H_DIM + k];
        w.z = W_hh[(2 * H_DIM + hu) * H_DIM + k];
        w.w = W_hh[(3 * H_DIM + hu) * H_DIM + k];
        g_Wt4[e] = w;
    }
    for (int e = idx; e < I_DIM * H_DIM; e += stride) {
        int i = e / H_DIM, hu = e % H_DIM;
        float4 w;
        w.x = W_ih[(0 * H_DIM + hu) * I_DIM + i];
        w.y = W_ih[(1 * H_DIM + hu) * I_DIM + i];
        w.z = W_ih[(2 * H_DIM + hu) * I_DIM + i];
        w.w = W_ih[(3 * H_DIM + hu) * I_DIM + i];
        g_Wit4[e] = w;
    }
    for (int e = idx; e < G_DIM; e += stride)
        g_bs[e] = b_ih[e] + b_hh[e];
}

// ---- packed f32x2 helpers (sm_100+) ---------------------------------------
__device__ __forceinline__ u64 pack2(float lo, float hi) {
    u64 r; asm("mov.b64 %0, {%1, %2};" : "=l"(r) : "f"(lo), "f"(hi)); return r;
}
__device__ __forceinline__ u64 fma2(u64 a, u64 b, u64 c) {
    u64 d; asm("fma.rn.f32x2 %0, %1, %2, %3;" : "=l"(d) : "l"(a), "l"(b), "l"(c)); return d;
}
__device__ __forceinline__ void unpack2(u64 v, float& lo, float& hi) {
    asm("mov.b64 {%0, %1}, %2;" : "=f"(lo), "=f"(hi) : "l"(v));
}

// ---- accurate fast activations (MUFU EX2/RCP path, err ~1e-6) -------------
__device__ __forceinline__ float sigmoid_f(float x) {
    return 1.0f / (1.0f + __expf(-x));
}
__device__ __forceinline__ float tanh_f(float x) {
    float a = fabsf(x);
    float e = __expf(-2.0f * a);
    float r = (1.0f - e) / (1.0f + e);
    return copysignf(r, x);
}

// ---------------------------------------------------------------------------
__global__ __launch_bounds__(THREADS, 2)
void lstm_kernel(const float* __restrict__ x,    // [B, T, I]
                 const float* __restrict__ W1,   // [OUT, T*H]
                 const float* __restrict__ b1,   // [OUT]
                 float* __restrict__ out) {      // [B, OUT]
    // h transposed: [buf][k][j], pair (j, j+1) contiguous -> LDS.64 broadcast
    __shared__ float h_s[2][H_DIM][HPITCH];
    // x transposed: [t][i][j]
    __shared__ float x_s[T_SEQ][I_DIM][BT];

    const int tid = threadIdx.x;
    const int b0  = blockIdx.x * BT;
    const int hu  = tid;  // each thread owns one hidden unit

    // Stage input tile into shared (transposed)
    for (int e = tid; e < BT * T_SEQ * I_DIM; e += THREADS) {
        int b = e / (T_SEQ * I_DIM), r = e % (T_SEQ * I_DIM);
        x_s[r / I_DIM][r % I_DIM][b] = x[(size_t)(b0 + b) * (T_SEQ * I_DIM) + r];
    }
    // h0 = 0
    for (int e = tid; e < H_DIM * HPITCH; e += THREADS)
        (&h_s[0][0][0])[e] = 0.0f;

    // Per-thread gate-bias pairs (same bias in both lanes of the pair)
    u64 binit[4];
    #pragma unroll
    for (int g = 0; g < 4; g++) {
        float b = g_bs[g * H_DIM + hu];
        binit[g] = pack2(b, b);
    }

    // Cell state: thread owns c[b][hu] for all BT batch rows
    float c[BT];
    #pragma unroll
    for (int j = 0; j < BT; j++) c[j] = 0.0f;

    // Output-head ownership: threads 0..BT*OUT-1 each own one (b, o) pair
    const int  pb = tid / OUT_DIM, po = tid % OUT_DIM;
    const bool do_proj = (tid < BT * OUT_DIM);
    float oacc = 0.0f;

    __syncthreads();

    int cur = 0;
    #pragma unroll 1
    for (int t = 0; t < T_SEQ; t++) {
        const int nxt = cur ^ 1;

        // Gate accumulators: [gate][pair] packed f32x2 over (j, j+1)
        u64 acc0[NPAIR], acc1[NPAIR], acc2[NPAIR], acc3[NPAIR];
        #pragma unroll
        for (int p = 0; p < NPAIR; p++) {
            acc0[p] = binit[0]; acc1[p] = binit[1];
            acc2[p] = binit[2]; acc3[p] = binit[3];
        }

        // ---- input projection: K = 13 ----
        #pragma unroll
        for (int i = 0; i < I_DIM; i++) {
            const float4 w4 = g_Wit4[i * H_DIM + hu];   // LDG.128, coalesced
            const u64 wb0 = pack2(w4.x, w4.x);
            const u64 wb1 = pack2(w4.y, w4.y);
            const u64 wb2 = pack2(w4.z, w4.z);
            const u64 wb3 = pack2(w4.w, w4.w);
            #pragma unroll
            for (int p = 0; p < NPAIR; p++) {
                const u64 hp = *(const u64*)&x_s[t][i][2 * p];  // LDS.64 broadcast
                acc0[p] = fma2(hp, wb0, acc0[p]);
                acc1[p] = fma2(hp, wb1, acc1[p]);
                acc2[p] = fma2(hp, wb2, acc2[p]);
                acc3[p] = fma2(hp, wb3, acc3[p]);
            }
        }

        // ---- hidden projection: K = 256 (the hot loop) ----
        #pragma unroll 4
        for (int k = 0; k < H_DIM; k++) {
            const float4 w4 = g_Wt4[k * H_DIM + hu];    // LDG.128, coalesced
            const u64 wb0 = pack2(w4.x, w4.x);
            const u64 wb1 = pack2(w4.y, w4.y);
            const u64 wb2 = pack2(w4.z, w4.z);
            const u64 wb3 = pack2(w4.w, w4.w);
            #pragma unroll
            for (int p = 0; p < NPAIR; p++) {
                const u64 hp = *(const u64*)&h_s[cur][k][2 * p];  // LDS.64 broadcast
                acc0[p] = fma2(hp, wb0, acc0[p]);
                acc1[p] = fma2(hp, wb1, acc1[p]);
                acc2[p] = fma2(hp, wb2, acc2[p]);
                acc3[p] = fma2(hp, wb3, acc3[p]);
            }
        }

        // ---- gates, state update, write h(t) (transposed) ----
        #pragma unroll
        for (int p = 0; p < NPAIR; p++) {
            float i0, i1, f0, f1, g0, g1, o0, o1;
            unpack2(acc0[p], i0, i1);
            unpack2(acc1[p], f0, f1);
            unpack2(acc2[p], g0, g1);
            unpack2(acc3[p], o0, o1);

            const float ia = sigmoid_f(i0), ib = sigmoid_f(i1);
            const float fa = sigmoid_f(f0), fb = sigmoid_f(f1);
            const float ga = tanh_f(g0),    gb = tanh_f(g1);
            const float oa = sigmoid_f(o0), ob = sigmoid_f(o1);

            const float ca = fmaf(fa, c[2 * p],     ia * ga);
            const float cb = fmaf(fb, c[2 * p + 1], ib * gb);
            c[2 * p]     = ca;
            c[2 * p + 1] = cb;

            const float ha = oa * tanh_f(ca);
            const float hb = ob * tanh_f(cb);
            *(u64*)&h_s[nxt][hu][2 * p] = pack2(ha, hb);  // STS.64
        }
        __syncthreads();   // h(t) complete & visible

        // ---- fold output head for this timestep (tiny) ----
        if (do_proj) {
            const float* w1p = W1 + (size_t)po * (T_SEQ * H_DIM) + t * H_DIM;
            float s = 0.0f;
            #pragma unroll 4
            for (int k = 0; k < H_DIM; k++)
                s = fmaf(h_s[nxt][k][pb], w1p[k], s);
            oacc += s;
        }
        cur = nxt;
        // No extra sync: next iter writes the other buffer; the buffer the
        // projection reads isn't re-written until after the next sync.
    }

    if (do_proj)
        out[(size_t)(b0 + pb) * OUT_DIM + po] = oacc + b1[po];
}

// ---------------------------------------------------------------------------
extern "C" void kernel_launch(void* const* d_in, const int* in_sizes, int n_in,
                              void* d_out, int out_size) {
    const float* x    = (const float*)d_in[0];  // input_seq [B,5,13]
    const float* W_ih = (const float*)d_in[1];  // [1024,13]
    const float* W_hh = (const float*)d_in[2];  // [1024,256]
    const float* b_ih = (const float*)d_in[3];  // [1024]
    const float* b_hh = (const float*)d_in[4];  // [1024]
    const float* W1   = (const float*)d_in[5];  // [6,1280]
    const float* b1   = (const float*)d_in[6];  // [6]
    float* out = (float*)d_out;                 // [B,6]

    prep_kernel<<<256, 256>>>(W_ih, W_hh, b_ih, b_hh);
    lstm_kernel<<<B_TOTAL / BT, THREADS>>>(x, W1, b1, out);
}

// round 7
// speedup vs baseline: 3.1218x; 1.5116x over previous
#include <cuda_runtime.h>
#include <cstdint>

typedef unsigned int u32;

// ---------------- problem constants ----------------
#define B_TOTAL 131072
#define T_SEQ   5
#define I_DIM   13
#define H_DIM   256
#define G_DIM   1024
#define OUT_DIM 6
#define XROW    (T_SEQ * I_DIM)      // 65

// ---------------- kernel config --------------------
#define TILE_M   64
#define THREADS  256
#define KREAL    272                 // 256 h + 13 x + 3 zero-pad
#define NCHUNK   64                  // gate-cols per W chunk
#define NCHUNKS  16

// smem strides (floats)
#define HS 260                       // 256 + 4 pad
#define XS 20                        // 16 + 4 pad
#define WS 276                       // 272 + 4 pad

// smem offsets (floats)
#define OFF_H0   0
#define OFF_H1   (TILE_M * HS)                   // 16640
#define OFF_X    (2 * TILE_M * HS)               // 33280
#define OFF_W    (OFF_X + TILE_M * XS)           // 34560
#define OFF_W1   (OFF_W + NCHUNK * WS)           // 52224
#define OFF_BIAS (OFF_W1 + OUT_DIM * H_DIM)      // 53760
#define OFF_OUT  (OFF_BIAS + G_DIM)              // 54784
#define SMEM_FLOATS (OFF_OUT + TILE_M * OUT_DIM) // 55168
#define SMEM_BYTES  (SMEM_FLOATS * 4)            // 220672

// ---------------- device scratch -------------------
// W packed: [chunk][n 0..63][k 0..271], n' = chunk*64+n = hu*4+gate, tf32-rounded
__device__ float g_W[NCHUNKS * NCHUNK * KREAL];
__device__ float g_bias[G_DIM];                        // interleaved n'
__device__ float g_c[(size_t)H_DIM * B_TOTAL];         // c state [hu][b]

// ---------------- helpers --------------------------
__device__ __forceinline__ u32 smem_u32(const void* p) {
    u32 a;
    asm("{ .reg .u64 t; cvta.to.shared.u64 t, %1; cvt.u32.u64 %0, t; }"
        : "=r"(a) : "l"(p));
    return a;
}
// FIXED: tf32 cvt destination must be a .b32 register
__device__ __forceinline__ float to_tf32(float x) {
    u32 r; asm("cvt.rna.tf32.f32 %0, %1;" : "=r"(r) : "f"(x));
    return __uint_as_float(r);
}
__device__ __forceinline__ void cp_async16(u32 dst, const float* src) {
    asm volatile("cp.async.cg.shared.global [%0], [%1], 16;"
                 :: "r"(dst), "l"(src) : "memory");
}
#define CP_COMMIT() asm volatile("cp.async.commit_group;" ::: "memory")
#define CP_WAIT0()  asm volatile("cp.async.wait_group 0;" ::: "memory")

__device__ __forceinline__ void mma8(float& d0, float& d1, float& d2, float& d3,
                                     float a0, float a1, float a2, float a3,
                                     float b0, float b1) {
    asm volatile(
        "mma.sync.aligned.m16n8k8.row.col.f32.tf32.tf32.f32 "
        "{%0,%1,%2,%3}, {%4,%5,%6,%7}, {%8,%9}, {%0,%1,%2,%3};"
        : "+f"(d0), "+f"(d1), "+f"(d2), "+f"(d3)
        : "r"(__float_as_uint(a0)), "r"(__float_as_uint(a1)),
          "r"(__float_as_uint(a2)), "r"(__float_as_uint(a3)),
          "r"(__float_as_uint(b0)), "r"(__float_as_uint(b1)));
}

__device__ __forceinline__ float sigmoid_f(float x) {
    return 1.0f / (1.0f + __expf(-x));
}
__device__ __forceinline__ float tanh_f(float x) {
    float a = fabsf(x);
    float e = __expf(-2.0f * a);
    float r = (1.0f - e) / (1.0f + e);
    return copysignf(r, x);
}

// ---------------- prep kernel ----------------------
__global__ void prep_kernel(const float* __restrict__ W_ih,
                            const float* __restrict__ W_hh,
                            const float* __restrict__ b_ih,
                            const float* __restrict__ b_hh) {
    int idx = blockIdx.x * blockDim.x + threadIdx.x;
    int stride = gridDim.x * blockDim.x;
    const int TOT = NCHUNKS * NCHUNK * KREAL;
    for (int e = idx; e < TOT; e += stride) {
        int np = e / KREAL;          // n' = chunk*64 + n  (already interleaved)
        int k  = e % KREAL;
        int hu = np >> 2, gate = np & 3;
        int orig = gate * H_DIM + hu;
        float v = 0.0f;
        if (k < H_DIM)                 v = W_hh[orig * H_DIM + k];
        else if (k < H_DIM + I_DIM)    v = W_ih[orig * I_DIM + (k - H_DIM)];
        g_W[e] = to_tf32(v);
    }
    for (int e = idx; e < G_DIM; e += stride) {
        int hu = e >> 2, gate = e & 3;
        int orig = gate * H_DIM + hu;
        g_bias[e] = b_ih[orig] + b_hh[orig];
    }
}

// ---------------- main fused kernel ----------------
__global__ __launch_bounds__(THREADS, 1)
void lstm_kernel(const float* __restrict__ x,
                 const float* __restrict__ W1,
                 const float* __restrict__ b1,
                 float* __restrict__ out) {
    extern __shared__ float sm[];
    const u32 sb  = smem_u32(sm);
    const int tid = threadIdx.x;
    const int b0  = blockIdx.x * TILE_M;

    const int wid  = tid >> 5;
    const int lane = tid & 31;
    const int g    = lane >> 2;      // fragment group row 0..7
    const int t4   = lane & 3;
    const int rt   = wid >> 1;       // row tile (16 rows)
    const int nh   = wid & 1;        // n half within chunk (32 cols)
    const int r0   = rt * 16;

    // lane's fixed batch row (epilogue ownership)
    const int myrow = r0 + g + ((t4 & 1) ? 8 : 0);
    const int hu_sel = (t4 >= 2) ? 1 : 0;
    const bool even  = ((t4 & 1) == 0);

    // ---- one-time staging ----
    for (int e = tid; e < TILE_M * XS; e += THREADS) sm[OFF_X + e] = 0.0f;
    for (int e = tid; e < G_DIM; e += THREADS) sm[OFF_BIAS + e] = g_bias[e];
    for (int e = tid; e < TILE_M * OUT_DIM; e += THREADS) sm[OFF_OUT + e] = 0.0f;

    float oacc[OUT_DIM];
    #pragma unroll
    for (int o = 0; o < OUT_DIM; o++) oacc[o] = 0.0f;

    #pragma unroll 1
    for (int t = 0; t < T_SEQ; t++) {
        const bool first = (t == 0);
        const bool last  = (t == T_SEQ - 1);
        const int hp = OFF_H0 + (t & 1) * (TILE_M * HS);        // h read (ping)
        const int hn = OFF_H0 + ((t + 1) & 1) * (TILE_M * HS);  // h write (pong)

        // stage x_t (tf32) and W1 slice for this t
        for (int e = tid; e < TILE_M * I_DIM; e += THREADS) {
            int row = e / I_DIM, i = e % I_DIM;
            sm[OFF_X + row * XS + i] =
                to_tf32(x[(size_t)(b0 + row) * XROW + t * I_DIM + i]);
        }
        for (int e = tid; e < OUT_DIM * H_DIM; e += THREADS)
            sm[OFF_W1 + e] = W1[(e / H_DIM) * (T_SEQ * H_DIM) + t * H_DIM + (e % H_DIM)];
        // (visibility guaranteed by the post-cp sync below)

        #pragma unroll 1
        for (int chunk = 0; chunk < NCHUNKS; chunk++) {
            // ---- load W chunk into smem (single buffer) ----
            {
                const float* srcb = g_W + (size_t)chunk * NCHUNK * KREAL;
                const u32 dbase = sb + OFF_W * 4;
                #pragma unroll
                for (int i = 0; i < 17; i++) {
                    int e  = tid + i * THREADS;       // 0..4351 float4 slots
                    int rw = e / 68, c16 = e % 68;
                    cp_async16(dbase + (u32)(rw * WS + c16 * 4) * 4,
                               srcb + (size_t)rw * KREAL + c16 * 4);
                }
                CP_COMMIT();
                CP_WAIT0();
            }
            __syncthreads();   // W ready; x/W1 staging also visible

            // ---- prefetch c for this chunk ----
            float cold[4];
            #pragma unroll
            for (int nt = 0; nt < 4; nt++) {
                const int hu = chunk * 16 + nh * 8 + nt * 2 + hu_sel;
                cold[nt] = first ? 0.0f : g_c[(size_t)hu * B_TOTAL + b0 + myrow];
            }

            // ---- MMA: gates for 64 n-cols ----
            float d[4][4];
            #pragma unroll
            for (int nt = 0; nt < 4; nt++)
                #pragma unroll
                for (int q = 0; q < 4; q++) d[nt][q] = 0.0f;

            const float* Ah = sm + hp + (r0 + g) * HS;
            const float* Ax = sm + OFF_X + (r0 + g) * XS;
            const float* Wb = sm + OFF_W + (nh * 32 + g) * WS;

            if (!first) {
                #pragma unroll 4
                for (int s = 0; s < 32; s++) {
                    const int k = s * 8;
                    const float a0 = Ah[k + t4];
                    const float a1 = Ah[8 * HS + k + t4];
                    const float a2 = Ah[k + t4 + 4];
                    const float a3 = Ah[8 * HS + k + t4 + 4];
                    #pragma unroll
                    for (int nt = 0; nt < 4; nt++) {
                        const float b0f = Wb[nt * 8 * WS + k + t4];
                        const float b1f = Wb[nt * 8 * WS + k + t4 + 4];
                        mma8(d[nt][0], d[nt][1], d[nt][2], d[nt][3],
                             a0, a1, a2, a3, b0f, b1f);
                    }
                }
            }
            #pragma unroll
            for (int s = 32; s < 34; s++) {
                const int xk = (s - 32) * 8;
                const float a0 = Ax[xk + t4];
                const float a1 = Ax[8 * XS + xk + t4];
                const float a2 = Ax[xk + t4 + 4];
                const float a3 = Ax[8 * XS + xk + t4 + 4];
                #pragma unroll
                for (int nt = 0; nt < 4; nt++) {
                    const float b0f = Wb[nt * 8 * WS + s * 8 + t4];
                    const float b1f = Wb[nt * 8 * WS + s * 8 + t4 + 4];
                    mma8(d[nt][0], d[nt][1], d[nt][2], d[nt][3],
                         a0, a1, a2, a3, b0f, b1f);
                }
            }

            // ---- epilogue: gate exchange + cell update ----
            #pragma unroll
            for (int nt = 0; nt < 4; nt++) {
                // even lane (row g):   owns d0,d1 = (i,f); needs partner (g,o)
                // odd  lane (row g+8): owns d2,d3 = (g,o); needs partner (i,f)
                const float sx = even ? d[nt][2] : d[nt][0];
                const float sy = even ? d[nt][3] : d[nt][1];
                const float rx = __shfl_xor_sync(0xFFFFFFFFu, sx, 1);
                const float ry = __shfl_xor_sync(0xFFFFFFFFu, sy, 1);

                const float vi = even ? d[nt][0] : rx;
                const float vf = even ? d[nt][1] : ry;
                const float vg = even ? rx : d[nt][2];
                const float vo = even ? ry : d[nt][3];

                const int nb = chunk * 64 + nh * 32 + nt * 8 + hu_sel * 4;
                const float gi = vi + sm[OFF_BIAS + nb + 0];
                const float gf = vf + sm[OFF_BIAS + nb + 1];
                const float gg = vg + sm[OFF_BIAS + nb + 2];
                const float go = vo + sm[OFF_BIAS + nb + 3];

                const float i_ = sigmoid_f(gi);
                const float f_ = sigmoid_f(gf);
                const float g_ = tanh_f(gg);
                const float o_ = sigmoid_f(go);
                const float cn = fmaf(f_, cold[nt], i_ * g_);
                const float hv = o_ * tanh_f(cn);

                const int hu = chunk * 16 + nh * 8 + nt * 2 + hu_sel;
                if (!last) {
                    g_c[(size_t)hu * B_TOTAL + b0 + myrow] = cn;
                    sm[hn + myrow * HS + hu] = to_tf32(hv);
                }
                #pragma unroll
                for (int o = 0; o < OUT_DIM; o++)
                    oacc[o] = fmaf(hv, sm[OFF_W1 + o * H_DIM + hu], oacc[o]);
            }
            __syncthreads();   // protect WBUF reuse + h-pong ordering
        }
    }

    // ---- reduce head partials (4 lanes per row) and write out ----
    #pragma unroll
    for (int o = 0; o < OUT_DIM; o++)
        atomicAdd(&sm[OFF_OUT + myrow * OUT_DIM + o], oacc[o]);
    __syncthreads();
    for (int e = tid; e < TILE_M * OUT_DIM; e += THREADS) {
        const int row = e / OUT_DIM, o = e % OUT_DIM;
        out[(size_t)(b0 + row) * OUT_DIM + o] = sm[OFF_OUT + e] + b1[o];
    }
}

// ---------------------------------------------------------------------------
extern "C" void kernel_launch(void* const* d_in, const int* in_sizes, int n_in,
                              void* d_out, int out_size) {
    const float* x    = (const float*)d_in[0];
    const float* W_ih = (const float*)d_in[1];
    const float* W_hh = (const float*)d_in[2];
    const float* b_ih = (const float*)d_in[3];
    const float* b_hh = (const float*)d_in[4];
    const float* W1   = (const float*)d_in[5];
    const float* b1   = (const float*)d_in[6];
    float* out = (float*)d_out;

    cudaFuncSetAttribute(lstm_kernel,
                         cudaFuncAttributeMaxDynamicSharedMemorySize, SMEM_BYTES);

    prep_kernel<<<288, 256>>>(W_ih, W_hh, b_ih, b_hh);
    lstm_kernel<<<B_TOTAL / TILE_M, THREADS, SMEM_BYTES>>>(x, W1, b1, out);
}

// round 9
// speedup vs baseline: 4.2054x; 1.3471x over previous
#include <cuda_runtime.h>
#include <cstdint>

typedef unsigned int u32;

// ---------------- problem constants ----------------
#define B_TOTAL 131072
#define T_SEQ   5
#define I_DIM   13
#define H_DIM   256
#define G_DIM   1024
#define OUT_DIM 6
#define XROW    (T_SEQ * I_DIM)      // 65

// ---------------- kernel config --------------------
#define TILE_M   64
#define THREADS  256
#define NCHUNKS  16                  // 16 chunks x 64 gate-cols
#define WCHUNK   (8 * 34 * 64)       // floats per W chunk = 17408

// smem strides (floats)
#define HS 276                       // 276%32=20 -> conflict-free fragment loads
#define XS 20

// smem offsets (floats)
#define OFF_H    0                                 // 64*276 = 17664
#define OFF_X    17664                             // 64*20  = 1280
#define OFF_W    18944                             // 2*17408 = 34816
#define OFF_W1   53760                             // 1536
#define OFF_BIAS 55296                             // 1024
#define OFF_OUT  56320                             // 384
#define SMEM_FLOATS 56704
#define SMEM_BYTES  (SMEM_FLOATS * 4)              // 226816

// ---------------- device scratch -------------------
// W packed fragment-order: [chunk][ntg 0..7][s 0..33][g 0..7][p 0..7]
//   p=2*t4   -> orig k = s*8 + t4
//   p=2*t4+1 -> orig k = s*8 + t4 + 4
__device__ float g_W[NCHUNKS * WCHUNK];
__device__ float g_bias[G_DIM];                    // interleaved n' = hu*4+gate
__device__ float g_c[(size_t)H_DIM * B_TOTAL];     // c state [hu][b]

// ---------------- helpers --------------------------
__device__ __forceinline__ u32 smem_u32(const void* p) {
    u32 a;
    asm("{ .reg .u64 t; cvta.to.shared.u64 t, %1; cvt.u32.u64 %0, t; }"
        : "=r"(a) : "l"(p));
    return a;
}
__device__ __forceinline__ float to_tf32(float x) {
    u32 r; asm("cvt.rna.tf32.f32 %0, %1;" : "=r"(r) : "f"(x));
    return __uint_as_float(r);
}
__device__ __forceinline__ void cp_async16(u32 dst, const float* src) {
    asm volatile("cp.async.cg.shared.global [%0], [%1], 16;"
                 :: "r"(dst), "l"(src) : "memory");
}
#define CP_COMMIT() asm volatile("cp.async.commit_group;" ::: "memory")
#define CP_WAIT1()  asm volatile("cp.async.wait_group 1;" ::: "memory")

__device__ __forceinline__ void mma8(float& d0, float& d1, float& d2, float& d3,
                                     float a0, float a1, float a2, float a3,
                                     float b0, float b1) {
    asm volatile(
        "mma.sync.aligned.m16n8k8.row.col.f32.tf32.tf32.f32 "
        "{%0,%1,%2,%3}, {%4,%5,%6,%7}, {%8,%9}, {%0,%1,%2,%3};"
        : "+f"(d0), "+f"(d1), "+f"(d2), "+f"(d3)
        : "r"(__float_as_uint(a0)), "r"(__float_as_uint(a1)),
          "r"(__float_as_uint(a2)), "r"(__float_as_uint(a3)),
          "r"(__float_as_uint(b0)), "r"(__float_as_uint(b1)));
}

__device__ __forceinline__ float sigmoid_f(float x) {
    return 1.0f / (1.0f + __expf(-x));
}
__device__ __forceinline__ float tanh_f(float x) {
    float a = fabsf(x);
    float e = __expf(-2.0f * a);
    float r = (1.0f - e) / (1.0f + e);
    return copysignf(r, x);
}
// interleaved slot for orig within-group index j (0..7)
__device__ __forceinline__ int islot(int j) {
    return ((j & 3) << 1) | (j >> 2);
}

// ---------------- prep kernel ----------------------
__global__ void prep_kernel(const float* __restrict__ W_ih,
                            const float* __restrict__ W_hh,
                            const float* __restrict__ b_ih,
                            const float* __restrict__ b_hh) {
    int idx = blockIdx.x * blockDim.x + threadIdx.x;
    int stride = gridDim.x * blockDim.x;
    const int TOT = NCHUNKS * WCHUNK;
    for (int e = idx; e < TOT; e += stride) {
        int rem = e;
        int inner = rem & 63;  rem >>= 6;
        int s     = rem % 34;  rem /= 34;
        int ntg   = rem & 7;   rem >>= 3;
        int chunk = rem;
        int gg = inner >> 3, p = inner & 7;
        int k = s * 8 + (p >> 1) + ((p & 1) << 2);
        int col = chunk * 64 + ntg * 8 + gg;          // interleaved n'
        int hu = col >> 2, gate = col & 3;
        int r = gate * H_DIM + hu;
        float v = 0.0f;
        if (k < H_DIM)                 v = W_hh[r * H_DIM + k];
        else if (k < H_DIM + I_DIM)    v = W_ih[r * I_DIM + (k - H_DIM)];
        g_W[e] = to_tf32(v);
    }
    for (int e = idx; e < G_DIM; e += stride) {
        int hu = e >> 2, gate = e & 3;
        g_bias[e] = b_ih[gate * H_DIM + hu] + b_hh[gate * H_DIM + hu];
    }
}

// ---------------- main fused kernel ----------------
__global__ __launch_bounds__(THREADS, 1)
void lstm_kernel(const float* __restrict__ x,
                 const float* __restrict__ W1,
                 const float* __restrict__ b1,
                 float* __restrict__ out) {
    extern __shared__ float sm[];
    const u32 sb  = smem_u32(sm);
    const int tid = threadIdx.x;
    const int b0  = blockIdx.x * TILE_M;

    const int wid  = tid >> 5;
    const int lane = tid & 31;
    const int g    = lane >> 2;
    const int t4   = lane & 3;
    const int rt   = wid >> 1;
    const int nh   = wid & 1;
    const int r0   = rt * 16;

    const int myrow  = r0 + g + ((t4 & 1) ? 8 : 0);
    const int hu_sel = t4 >> 1;
    const bool even  = ((t4 & 1) == 0);

    // ---- one-time staging ----
    for (int e = tid; e < TILE_M * XS; e += THREADS) sm[OFF_X + e] = 0.0f;
    for (int e = tid; e < G_DIM; e += THREADS) sm[OFF_BIAS + e] = g_bias[e];
    for (int e = tid; e < TILE_M * OUT_DIM; e += THREADS) sm[OFF_OUT + e] = 0.0f;

    // ---- prologue: prefetch chunk 0 into buf 0 ----
    {
        const u32 dst = sb + OFF_W * 4;
        #pragma unroll
        for (int i = 0; i < 17; i++) {
            int e = tid + i * THREADS;
            cp_async16(dst + (u32)e * 16, g_W + (size_t)e * 4);
        }
        CP_COMMIT();
    }
    __syncthreads();   // x-zero / bias visible before later use

    float oacc[OUT_DIM];
    #pragma unroll
    for (int o = 0; o < OUT_DIM; o++) oacc[o] = 0.0f;

    #pragma unroll 1
    for (int t = 0; t < T_SEQ; t++) {
        const bool first = (t == 0);
        const bool last  = (t == T_SEQ - 1);

        // ---- stage x_t (interleaved, tf32) and W1 slice ----
        for (int e = tid; e < TILE_M * I_DIM; e += THREADS) {
            int row = e / I_DIM, i = e % I_DIM;
            int slot = (i >> 3) * 8 + islot(i & 7);
            sm[OFF_X + row * XS + slot] =
                to_tf32(x[(size_t)(b0 + row) * XROW + t * I_DIM + i]);
        }
        for (int e = tid; e < OUT_DIM * H_DIM; e += THREADS)
            sm[OFF_W1 + e] = W1[(e >> 8) * (T_SEQ * H_DIM) + t * H_DIM + (e & 255)];
        __syncthreads();   // staging + prior-step h writes visible

        // ---- load A fragments into registers (once per t) ----
        float2 ahA[32], ahB[32], axA[2], axB[2];
        const float2* Ah2 = (const float2*)(sm + OFF_H) + (size_t)(r0 + g) * (HS / 2);
        if (!first) {
            #pragma unroll
            for (int s = 0; s < 32; s++) {
                ahA[s] = Ah2[s * 4 + t4];
                ahB[s] = Ah2[8 * (HS / 2) + s * 4 + t4];
            }
        }
        const float2* Ax2 = (const float2*)(sm + OFF_X) + (r0 + g) * (XS / 2);
        #pragma unroll
        for (int s2 = 0; s2 < 2; s2++) {
            axA[s2] = Ax2[s2 * 4 + t4];
            axB[s2] = Ax2[8 * (XS / 2) + s2 * 4 + t4];
        }

        #pragma unroll 1
        for (int chunk = 0; chunk < NCHUNKS; chunk++) {
            const int giter = t * NCHUNKS + chunk;
            const int buf   = giter & 1;

            // ---- prefetch next chunk into other buffer ----
            if (giter < T_SEQ * NCHUNKS - 1) {
                const int nc = (chunk + 1) & (NCHUNKS - 1);
                const float* src = g_W + (size_t)nc * WCHUNK;
                const u32 dst = sb + (u32)(OFF_W + (buf ^ 1) * WCHUNK) * 4;
                #pragma unroll
                for (int i = 0; i < 17; i++) {
                    int e = tid + i * THREADS;
                    cp_async16(dst + (u32)e * 16, src + (size_t)e * 4);
                }
            }
            CP_COMMIT();
            CP_WAIT1();        // current chunk's data landed
            __syncthreads();

            // ---- prefetch c ----
            float cold[4];
            #pragma unroll
            for (int nt = 0; nt < 4; nt++) {
                const int hu = chunk * 16 + (nh * 4 + nt) * 2 + hu_sel;
                cold[nt] = first ? 0.0f : g_c[(size_t)hu * B_TOTAL + b0 + myrow];
            }

            // ---- MMA: all B loads contiguous conflict-free LDS.64 ----
            float d[4][4];
            #pragma unroll
            for (int nt = 0; nt < 4; nt++)
                #pragma unroll
                for (int q = 0; q < 4; q++) d[nt][q] = 0.0f;

            const float2* Wb2 = (const float2*)(sm + OFF_W + buf * WCHUNK)
                                + nh * 4 * 34 * 32 + 4 * g + t4;
            if (!first) {
                #pragma unroll
                for (int s = 0; s < 32; s++) {
                    #pragma unroll
                    for (int nt = 0; nt < 4; nt++) {
                        const float2 bp = Wb2[(nt * 34 + s) * 32];
                        mma8(d[nt][0], d[nt][1], d[nt][2], d[nt][3],
                             ahA[s].x, ahB[s].x, ahA[s].y, ahB[s].y, bp.x, bp.y);
                    }
                }
            }
            #pragma unroll
            for (int s2 = 0; s2 < 2; s2++) {
                #pragma unroll
                for (int nt = 0; nt < 4; nt++) {
                    const float2 bp = Wb2[(nt * 34 + 32 + s2) * 32];
                    mma8(d[nt][0], d[nt][1], d[nt][2], d[nt][3],
                         axA[s2].x, axB[s2].x, axA[s2].y, axB[s2].y, bp.x, bp.y);
                }
            }

            // ---- epilogue ----
            #pragma unroll
            for (int nt = 0; nt < 4; nt++) {
                const int ntg = nh * 4 + nt;
                const float sx = even ? d[nt][2] : d[nt][0];
                const float sy = even ? d[nt][3] : d[nt][1];
                const float rx = __shfl_xor_sync(0xFFFFFFFFu, sx, 1);
                const float ry = __shfl_xor_sync(0xFFFFFFFFu, sy, 1);

                const float vi = even ? d[nt][0] : rx;
                const float vf = even ? d[nt][1] : ry;
                const float vg = even ? rx : d[nt][2];
                const float vo = even ? ry : d[nt][3];

                const int nb = chunk * 64 + ntg * 8 + hu_sel * 4;
                const float gi = vi + sm[OFF_BIAS + nb + 0];
                const float gf = vf + sm[OFF_BIAS + nb + 1];
                const float gg = vg + sm[OFF_BIAS + nb + 2];
                const float go = vo + sm[OFF_BIAS + nb + 3];

                const float i_ = sigmoid_f(gi);
                const float f_ = sigmoid_f(gf);
                const float g_ = tanh_f(gg);
                const float o_ = sigmoid_f(go);
                const float cn = fmaf(f_, cold[nt], i_ * g_);
                const float hv = o_ * tanh_f(cn);

                const int hu = chunk * 16 + ntg * 2 + hu_sel;
                if (!last) {
                    g_c[(size_t)hu * B_TOTAL + b0 + myrow] = cn;
                    const int j = hu & 7;
                    sm[OFF_H + myrow * HS + (hu >> 3) * 8 + islot(j)] = to_tf32(hv);
                }
                #pragma unroll
                for (int o = 0; o < OUT_DIM; o++)
                    oacc[o] = fmaf(hv, sm[OFF_W1 + o * H_DIM + hu], oacc[o]);
            }
            __syncthreads();   // buffer reuse + h-write ordering
        }
    }

    // ---- reduce head partials and write out ----
    #pragma unroll
    for (int o = 0; o < OUT_DIM; o++)
        atomicAdd(&sm[OFF_OUT + myrow * OUT_DIM + o], oacc[o]);
    __syncthreads();
    for (int e = tid; e < TILE_M * OUT_DIM; e += THREADS) {
        const int row = e / OUT_DIM, o = e % OUT_DIM;
        out[(size_t)(b0 + row) * OUT_DIM + o] = sm[OFF_OUT + e] + b1[o];
    }
}

// ---------------------------------------------------------------------------
extern "C" void kernel_launch(void* const* d_in, const int* in_sizes, int n_in,
                              void* d_out, int out_size) {
    const float* x    = (const float*)d_in[0];
    const float* W_ih = (const float*)d_in[1];
    const float* W_hh = (const float*)d_in[2];
    const float* b_ih = (const float*)d_in[3];
    const float* b_hh = (const float*)d_in[4];
    const float* W1   = (const float*)d_in[5];
    const float* b1   = (const float*)d_in[6];
    float* out = (float*)d_out;

    cudaFuncSetAttribute(lstm_kernel,
                         cudaFuncAttributeMaxDynamicSharedMemorySize, SMEM_BYTES);

    prep_kernel<<<288, 256>>>(W_ih, W_hh, b_ih, b_hh);
    lstm_kernel<<<B_TOTAL / TILE_M, THREADS, SMEM_BYTES>>>(x, W1, b1, out);
}

// round 10
// speedup vs baseline: 11.2812x; 2.6825x over previous
#include <cuda_runtime.h>
#include <cuda_fp16.h>
#include <cstdint>

typedef unsigned int u32;

// ---------------- problem constants ----------------
#define B_TOTAL 131072
#define T_SEQ   5
#define I_DIM   13
#define H_DIM   256
#define G_DIM   1024
#define OUT_DIM 6
#define XROW    (T_SEQ * I_DIM)      // 65

// ---------------- kernel config --------------------
#define TILE_M   64
#define THREADS  256
#define NCHUNKS  16                  // 16 chunks x 64 gate-cols
#define KSTEPS   17                  // 272 / 16 (fp16 K per MMA = 16)
#define WCHUNK_H 17408               // halves per W chunk (8 ntg * 17 s * 128)
#define WBYTES   34816               // bytes per W chunk buffer

// h buffer: 64 rows x 280 halves (272 used: 256 h + 16 x), stride 560 B
#define HSH  280
#define HB   560

// smem offsets (BYTES)
#define OFF_H    0                    // 35840
#define OFF_W    35840                // 2 x 34816 = 69632
#define OFF_BIAS 105472               // 1024 f32 = 4096
#define OFF_W1   109568               // 1536 halves = 3072
#define OFF_OUT  112640               // 384 f32 = 1536
#define SMEM_BYTES 114176

// ---------------- device scratch -------------------
// W packed fp16 fragment-order: [chunk][ntg 0..7][s 0..16][g 0..7][slot 0..7][b 0..1]
__device__ __half g_W[NCHUNKS * WCHUNK_H];
__device__ float  g_bias[G_DIM];                   // interleaved n' = hu*4+gate
__device__ float  g_c[(size_t)H_DIM * B_TOTAL];    // c state [hu][b]

// ---------------- helpers --------------------------
__device__ __forceinline__ u32 smem_u32(const void* p) {
    u32 a;
    asm("{ .reg .u64 t; cvta.to.shared.u64 t, %1; cvt.u32.u64 %0, t; }"
        : "=r"(a) : "l"(p));
    return a;
}
__device__ __forceinline__ void cp_async16(u32 dst, const void* src) {
    asm volatile("cp.async.cg.shared.global [%0], [%1], 16;"
                 :: "r"(dst), "l"(src) : "memory");
}
#define CP_COMMIT() asm volatile("cp.async.commit_group;" ::: "memory")
#define CP_WAIT1()  asm volatile("cp.async.wait_group 1;" ::: "memory")

__device__ __forceinline__ void mma16(float& d0, float& d1, float& d2, float& d3,
                                      u32 a0, u32 a1, u32 a2, u32 a3,
                                      u32 b0, u32 b1) {
    asm volatile(
        "mma.sync.aligned.m16n8k16.row.col.f32.f16.f16.f32 "
        "{%0,%1,%2,%3}, {%4,%5,%6,%7}, {%8,%9}, {%0,%1,%2,%3};"
        : "+f"(d0), "+f"(d1), "+f"(d2), "+f"(d3)
        : "r"(a0), "r"(a1), "r"(a2), "r"(a3), "r"(b0), "r"(b1));
}

__device__ __forceinline__ float tanh_a(float x) {
    float r; asm("tanh.approx.f32 %0, %1;" : "=f"(r) : "f"(x)); return r;
}
__device__ __forceinline__ float sigmoid_a(float x) {
    return fmaf(tanh_a(0.5f * x), 0.5f, 0.5f);
}
// position of within-16-block k index kk in fragment-interleaved order
__device__ __forceinline__ int pos16(int kk) {
    int j = kk >> 1, b = kk & 1;
    int slot = ((j & 3) << 1) | (j >> 2);
    return slot * 2 + b;
}

// ---------------- prep kernel ----------------------
__global__ void prep_kernel(const float* __restrict__ W_ih,
                            const float* __restrict__ W_hh,
                            const float* __restrict__ b_ih,
                            const float* __restrict__ b_hh) {
    int idx = blockIdx.x * blockDim.x + threadIdx.x;
    int stride = gridDim.x * blockDim.x;
    const int TOT = NCHUNKS * WCHUNK_H;
    for (int e = idx; e < TOT; e += stride) {
        int chunk = e / WCHUNK_H;
        int r1 = e % WCHUNK_H;
        int ntg = r1 / 2176;
        int r2 = r1 % 2176;
        int s  = r2 / 128;
        int r3 = r2 % 128;
        int g    = r3 >> 4;
        int slot = (r3 >> 1) & 7;
        int b    = r3 & 1;
        int j = (slot >> 1) | ((slot & 1) << 2);
        int k = s * 16 + j * 2 + b;
        int col = chunk * 64 + ntg * 8 + g;          // interleaved n'
        int hu = col >> 2, gate = col & 3;
        int r = gate * H_DIM + hu;
        float v = 0.0f;
        if (k < H_DIM)                 v = W_hh[r * H_DIM + k];
        else if (k < H_DIM + I_DIM)    v = W_ih[r * I_DIM + (k - H_DIM)];
        g_W[e] = __float2half(v);
    }
    for (int e = idx; e < G_DIM; e += stride) {
        int hu = e >> 2, gate = e & 3;
        g_bias[e] = b_ih[gate * H_DIM + hu] + b_hh[gate * H_DIM + hu];
    }
}

// ---------------- main fused kernel ----------------
__global__ __launch_bounds__(THREADS, 2)
void lstm_kernel(const float* __restrict__ x,
                 const float* __restrict__ W1,
                 const float* __restrict__ b1,
                 float* __restrict__ out) {
    extern __shared__ char smc[];
    const u32 sb  = smem_u32(smc);
    __half* hsm   = (__half*)(smc + OFF_H);
    float*  bias_s = (float*)(smc + OFF_BIAS);
    __half* w1s    = (__half*)(smc + OFF_W1);
    float*  out_s  = (float*)(smc + OFF_OUT);

    const int tid = threadIdx.x;
    const int b0  = blockIdx.x * TILE_M;

    const int wid  = tid >> 5;
    const int lane = tid & 31;
    const int g    = lane >> 2;
    const int t4   = lane & 3;
    const int rt   = wid >> 1;
    const int nh   = wid & 1;
    const int r0   = rt * 16;

    const int myrow  = r0 + g + ((t4 & 1) ? 8 : 0);
    const int hu_sel = t4 >> 1;
    const bool even  = ((t4 & 1) == 0);

    // ---- one-time staging: zero h (incl x region), bias, out ----
    for (int e = tid; e < TILE_M * HSH; e += THREADS) hsm[e] = __float2half(0.0f);
    for (int e = tid; e < G_DIM; e += THREADS) bias_s[e] = g_bias[e];
    for (int e = tid; e < TILE_M * OUT_DIM; e += THREADS) out_s[e] = 0.0f;

    // ---- prologue: prefetch chunk 0 into buf 0 ----
    {
        const u32 dst = sb + OFF_W;
        #pragma unroll
        for (int i = 0; i < 9; i++) {
            int e = tid + i * THREADS;
            if (e < WBYTES / 16)
                cp_async16(dst + (u32)e * 16, (const char*)g_W + (size_t)e * 16);
        }
        CP_COMMIT();
    }
    __syncthreads();

    float oacc[OUT_DIM];
    #pragma unroll
    for (int o = 0; o < OUT_DIM; o++) oacc[o] = 0.0f;

    #pragma unroll 1
    for (int t = 0; t < T_SEQ; t++) {
        const bool first = (t == 0);
        const bool last  = (t == T_SEQ - 1);

        // ---- stage x_t into h-buffer cols 256..271 + W1 slice (fp16) ----
        for (int e = tid; e < TILE_M * 16; e += THREADS) {
            int row = e >> 4, i = e & 15;
            float v = (i < I_DIM)
                ? x[(size_t)(b0 + row) * XROW + t * I_DIM + i] : 0.0f;
            hsm[row * HSH + 256 + pos16(i)] = __float2half(v);
        }
        for (int e = tid; e < OUT_DIM * H_DIM; e += THREADS)
            w1s[e] = __float2half(
                W1[(e >> 8) * (T_SEQ * H_DIM) + t * H_DIM + (e & 255)]);
        __syncthreads();   // staging + prior h writes visible

        // ---- load A fragments into registers (once per t) ----
        uint2 aL[KSTEPS], aH[KSTEPS];
        {
            const char* rowL = smc + OFF_H + (size_t)(r0 + g) * HB + t4 * 8;
            const char* rowH = rowL + 8 * HB;
            #pragma unroll
            for (int s = 0; s < KSTEPS; s++) {
                aL[s] = *(const uint2*)(rowL + s * 32);
                aH[s] = *(const uint2*)(rowH + s * 32);
            }
        }

        #pragma unroll 1
        for (int chunk = 0; chunk < NCHUNKS; chunk++) {
            const int giter = t * NCHUNKS + chunk;
            const int buf   = giter & 1;

            // ---- prefetch next chunk into other buffer ----
            if (giter < T_SEQ * NCHUNKS - 1) {
                const int nc = (chunk + 1) & (NCHUNKS - 1);
                const char* src = (const char*)(g_W + (size_t)nc * WCHUNK_H);
                const u32 dst = sb + OFF_W + (u32)(buf ^ 1) * WBYTES;
                #pragma unroll
                for (int i = 0; i < 9; i++) {
                    int e = tid + i * THREADS;
                    if (e < WBYTES / 16)
                        cp_async16(dst + (u32)e * 16, src + (size_t)e * 16);
                }
            }
            CP_COMMIT();
            CP_WAIT1();        // current chunk landed
            __syncthreads();

            // ---- prefetch c ----
            float cold[4];
            #pragma unroll
            for (int nt = 0; nt < 4; nt++) {
                const int hu = chunk * 16 + (nh * 4 + nt) * 2 + hu_sel;
                cold[nt] = first ? 0.0f : g_c[(size_t)hu * B_TOTAL + b0 + myrow];
            }

            // ---- MMA ----
            float d[4][4];
            #pragma unroll
            for (int nt = 0; nt < 4; nt++)
                #pragma unroll
                for (int q = 0; q < 4; q++) d[nt][q] = 0.0f;

            const char* wb = smc + OFF_W + buf * WBYTES
                             + (size_t)(nh * 4) * KSTEPS * 256 + g * 32 + t4 * 8;
            if (!first) {
                #pragma unroll
                for (int s = 0; s < KSTEPS; s++) {
                    #pragma unroll
                    for (int nt = 0; nt < 4; nt++) {
                        const uint2 bb = *(const uint2*)(wb + (nt * KSTEPS + s) * 256);
                        mma16(d[nt][0], d[nt][1], d[nt][2], d[nt][3],
                              aL[s].x, aH[s].x, aL[s].y, aH[s].y, bb.x, bb.y);
                    }
                }
            } else {
                const int s = 16;  // x-only block at t=0 (h == 0)
                #pragma unroll
                for (int nt = 0; nt < 4; nt++) {
                    const uint2 bb = *(const uint2*)(wb + (nt * KSTEPS + s) * 256);
                    mma16(d[nt][0], d[nt][1], d[nt][2], d[nt][3],
                          aL[s].x, aH[s].x, aL[s].y, aH[s].y, bb.x, bb.y);
                }
            }

            // ---- epilogue: gate exchange + cell update ----
            #pragma unroll
            for (int nt = 0; nt < 4; nt++) {
                const int ntg = nh * 4 + nt;
                const float sx = even ? d[nt][2] : d[nt][0];
                const float sy = even ? d[nt][3] : d[nt][1];
                const float rx = __shfl_xor_sync(0xFFFFFFFFu, sx, 1);
                const float ry = __shfl_xor_sync(0xFFFFFFFFu, sy, 1);

                const float vi = even ? d[nt][0] : rx;
                const float vf = even ? d[nt][1] : ry;
                const float vg = even ? rx : d[nt][2];
                const float vo = even ? ry : d[nt][3];

                const int nb = chunk * 64 + ntg * 8 + hu_sel * 4;
                const float gi = vi + bias_s[nb + 0];
                const float gf = vf + bias_s[nb + 1];
                const float gg = vg + bias_s[nb + 2];
                const float go = vo + bias_s[nb + 3];

                const float i_ = sigmoid_a(gi);
                const float f_ = sigmoid_a(gf);
                const float g_ = tanh_a(gg);
                const float o_ = sigmoid_a(go);
                const float cn = fmaf(f_, cold[nt], i_ * g_);
                const float hv = o_ * tanh_a(cn);

                const int hu = chunk * 16 + ntg * 2 + hu_sel;
                if (!last) {
                    g_c[(size_t)hu * B_TOTAL + b0 + myrow] = cn;
                    hsm[myrow * HSH + (hu >> 4) * 16 + pos16(hu & 15)] =
                        __float2half(hv);
                }
                #pragma unroll
                for (int o = 0; o < OUT_DIM; o++)
                    oacc[o] = fmaf(hv, __half2float(w1s[o * H_DIM + hu]), oacc[o]);
            }
            __syncthreads();   // buffer reuse + h-write ordering
        }
    }

    // ---- reduce head partials and write out ----
    #pragma unroll
    for (int o = 0; o < OUT_DIM; o++)
        atomicAdd(&out_s[myrow * OUT_DIM + o], oacc[o]);
    __syncthreads();
    for (int e = tid; e < TILE_M * OUT_DIM; e += THREADS) {
        const int row = e / OUT_DIM, o = e % OUT_DIM;
        out[(size_t)(b0 + row) * OUT_DIM + o] = out_s[e] + b1[o];
    }
}

// ---------------------------------------------------------------------------
extern "C" void kernel_launch(void* const* d_in, const int* in_sizes, int n_in,
                              void* d_out, int out_size) {
    const float* x    = (const float*)d_in[0];
    const float* W_ih = (const float*)d_in[1];
    const float* W_hh = (const float*)d_in[2];
    const float* b_ih = (const float*)d_in[3];
    const float* b_hh = (const float*)d_in[4];
    const float* W1   = (const float*)d_in[5];
    const float* b1   = (const float*)d_in[6];
    float* out = (float*)d_out;

    cudaFuncSetAttribute(lstm_kernel,
                         cudaFuncAttributeMaxDynamicSharedMemorySize, SMEM_BYTES);

    prep_kernel<<<288, 256>>>(W_ih, W_hh, b_ih, b_hh);
    lstm_kernel<<<B_TOTAL / TILE_M, THREADS, SMEM_BYTES>>>(x, W1, b1, out);
}